// round 10
// baseline (speedup 1.0000x reference)
#include <cuda_runtime.h>
#include <cstdint>

typedef unsigned long long ull;

// Problem constants
constexpr int NB = 16, NN = 8192, NPOINT = 1024, NSAMPLE = 32;
constexpr int M_TOTAL = NB * NPOINT * NSAMPLE;       // 524288 positions
constexpr float INV_N = 1.0f / (float)M_TOTAL;       // 2^-19, exact
constexpr int NEWXYZ_ELEMS = NB * NPOINT * 3;        // 49152

// -------- scratch (device globals; no allocation allowed) --------
__device__ float g_y1[(size_t)M_TOTAL * 64];
__device__ float g_y2[(size_t)M_TOTAL * 64];
__device__ float g_mx[(size_t)NB * NPOINT * 128];    // per-query raw max (pre-BN3)
__device__ int   g_idx[M_TOTAL];
__device__ float g_part1[4096 * 128];
__device__ float g_part2[4096 * 128];
__device__ float g_part3[8192 * 128];
__device__ float g_sc1[64],  g_sh1[64];
__device__ float g_sc2[64],  g_sh2[64];
__device__ float g_sc3[128], g_sh3[128];

// ---------------- helpers ----------------
__device__ __forceinline__ float to_tf32(float x) {
    unsigned u;
    asm("cvt.rna.tf32.f32 %0, %1;" : "=r"(u) : "f"(x));
    return __uint_as_float(u);
}
__device__ __forceinline__ float sqdist3(float dx, float dy, float dz) {
    return fmaf(dz, dz, fmaf(dy, dy, __fmul_rn(dx, dx)));
}
// m16n8k8 tf32 HMMA (PTX-portable on compute_103; runs on tensor pipes)
__device__ __forceinline__ void mma16n8k8(float* d, const uint32_t* a,
                                          const uint32_t* b) {
    asm volatile(
        "mma.sync.aligned.m16n8k8.row.col.f32.tf32.tf32.f32 "
        "{%0,%1,%2,%3}, {%4,%5,%6,%7}, {%8,%9}, {%0,%1,%2,%3};"
        : "+f"(d[0]), "+f"(d[1]), "+f"(d[2]), "+f"(d[3])
        : "r"(a[0]), "r"(a[1]), "r"(a[2]), "r"(a[3]), "r"(b[0]), "r"(b[1]));
}

// ---------------- 1) farthest point sampling ----------------
// One block per batch; 512 threads x 16 points in registers.
// xyz mirrored in smem; one __syncthreads per iteration; index found by
// leader-lane rescan (first-index tie-break preserved).
__global__ void __launch_bounds__(512) fps_kernel(const float* __restrict__ xyz,
                                                  float* __restrict__ newxyz) {
    extern __shared__ float sx[];   // [NN*3]
    const int b = blockIdx.x, tid = threadIdx.x;
    const float* X = xyz + (size_t)b * NN * 3;
    float px[16], py[16], pz[16], dd[16];
#pragma unroll
    for (int j = 0; j < 16; j++) {
        int p = tid * 16 + j;
        px[j] = X[p * 3 + 0]; py[j] = X[p * 3 + 1]; pz[j] = X[p * 3 + 2];
        dd[j] = 1e10f;
    }
    for (int e = tid; e < NN * 3; e += 512) sx[e] = X[e];

    __shared__ int swv[2][16];
    __shared__ int swi[2][16];
    __syncthreads();

    float cx = sx[0], cy = sx[1], cz = sx[2];
    float* outb = newxyz + (size_t)b * NPOINT * 3;
    const int lane = tid & 31, wid = tid >> 5;
    int buf = 0;

    for (int it = 0; it < NPOINT; ++it) {
        if (tid == 0) {
            outb[it * 3 + 0] = cx;
            outb[it * 3 + 1] = cy;
            outb[it * 3 + 2] = cz;
        }
        float best = -1.0f;
#pragma unroll
        for (int j = 0; j < 16; j++) {
            float dx = __fsub_rn(px[j], cx);
            float dy = __fsub_rn(py[j], cy);
            float dz = __fsub_rn(pz[j], cz);
            float d = sqdist3(dx, dy, dz);
            float nd = fminf(dd[j], d);
            dd[j] = nd;
            best = fmaxf(best, nd);
        }
        // warp argmax: nonneg float bits compare as ints
        int vb = __float_as_int(best);
        int wmax = __reduce_max_sync(0xffffffffu, vb);
        unsigned msk = __ballot_sync(0xffffffffu, vb == wmax);
        int ldr = __ffs(msk) - 1;               // lowest lane = lowest point idx
        int widx = 0;
        if (lane == ldr) {
#pragma unroll
            for (int j = 15; j >= 0; j--)       // descending -> first j wins
                if (__float_as_int(dd[j]) == wmax) widx = tid * 16 + j;
        }
        widx = __shfl_sync(0xffffffffu, widx, ldr);
        if (lane == 0) { swv[buf][wid] = wmax; swi[buf][wid] = widx; }
        __syncthreads();
        // all warps redundantly reduce the 16 warp results
        int l = lane & 15;
        int v2 = swv[buf][l], i2 = swi[buf][l];
        int m2 = __reduce_max_sync(0xffffffffu, v2);
        unsigned mk2 = __ballot_sync(0xffffffffu, v2 == m2);
        int l2 = __ffs(mk2) - 1;                // lands in 0..15 (mirrored halves)
        int f = __shfl_sync(0xffffffffu, i2, l2);
        cx = sx[f * 3 + 0]; cy = sx[f * 3 + 1]; cz = sx[f * 3 + 2];
        buf ^= 1;
    }
}

// ---------------- 2) ball query ----------------
__global__ void __launch_bounds__(256) ball_kernel(const float* __restrict__ xyz,
                                                   const float* __restrict__ newxyz,
                                                   int* __restrict__ gidx) {
    const int gwarp = (blockIdx.x * blockDim.x + threadIdx.x) >> 5;
    const int lane = threadIdx.x & 31;
    if (gwarp >= NB * NPOINT) return;
    const int b = gwarp >> 10;
    const float R2 = (float)(0.2 * 0.2);

    const float cx = newxyz[gwarp * 3 + 0];
    const float cy = newxyz[gwarp * 3 + 1];
    const float cz = newxyz[gwarp * 3 + 2];
    const float* X = xyz + (size_t)b * NN * 3;
    int* out = gidx + (size_t)gwarp * NSAMPLE;

    int cnt = 0;
    int first = NN - 1;
    for (int base = 0; base < NN; base += 32) {
        int j = base + lane;
        float dx = __fsub_rn(cx, X[j * 3 + 0]);
        float dy = __fsub_rn(cy, X[j * 3 + 1]);
        float dz = __fsub_rn(cz, X[j * 3 + 2]);
        float sq = sqdist3(dx, dy, dz);
        bool in = !(sq > R2);
        unsigned mask = __ballot_sync(0xffffffffu, in);
        if (mask) {
            if (cnt == 0) first = base + __ffs(mask) - 1;
            if (in) {
                int slot = cnt + __popc(mask & ((1u << lane) - 1u));
                if (slot < NSAMPLE) out[slot] = j;
            }
            cnt += __popc(mask);
            if (cnt >= NSAMPLE) break;
        }
    }
    if (cnt < NSAMPLE && lane >= cnt) out[lane] = first;
}

// ---------------- 3) HMMA tf32 GEMM per layer (K-split, 2 stages) ----------------
// Block = 128 threads (4 warps), tile = 128 positions x 64 outputs.
// MODE 1: gather 67ch -> y1.  MODE 2: y1 -> y2.
// MODE 3: y2 -> per-query max (no y3 materialization; BN3+max commute).
template <int MODE>
__global__ void __launch_bounds__(128) mma_kernel(
    const float* __restrict__ xyz, const float* __restrict__ points,
    const float* __restrict__ newxyz, const int* __restrict__ gidx,
    const float* __restrict__ yin,
    const float* __restrict__ scin, const float* __restrict__ shin,
    const float* __restrict__ W, const float* __restrict__ bias,
    float* __restrict__ yout, float* __restrict__ part) {
    constexpr int CIN = (MODE == 1) ? 67 : 64;
    constexpr int KP  = (MODE == 1) ? 72 : 64;
    constexpr int S0  = (MODE == 1) ? 40 : 32;   // stage-0 cols
    constexpr int S1  = KP - S0;                 // 32
    constexpr int STR_A = S0 + 4;                // 44 / 36
    constexpr int STR_B = KP + 4;                // 76 / 68
    constexpr int NK0 = S0 / 8, NK1 = S1 / 8;

    extern __shared__ float sm[];
    float* As = sm;                    // [128][STR_A]
    float* Bs = sm + 128 * STR_A;      // [64][STR_B]
    __shared__ float sSc[64], sSh[64], sBias[64];
    __shared__ float sNew[4][3];
    __shared__ float redS[2][64], redQ[2][64];

    const int tid = threadIdx.x;
    const int lane = tid & 31, w = tid >> 5;
    int m_tile, obase;
    if (MODE == 3) { m_tile = blockIdx.x >> 1; obase = (blockIdx.x & 1) << 6; }
    else           { m_tile = blockIdx.x;      obase = 0; }
    const int m0 = m_tile * 128;

    if (tid < 64) sBias[tid] = bias[obase + tid];
    if (MODE == 1) {
        if (tid < 12) ((float*)sNew)[tid] = newxyz[(m0 >> 5) * 3 + tid];
    } else {
        if (tid >= 64) { sSc[tid - 64] = scin[tid - 64]; sSh[tid - 64] = shin[tid - 64]; }
    }
    __syncthreads();

    // ---- B (weights, full K) ----
    for (int e = tid; e < 64 * KP; e += 128) {
        int o = e / KP, c = e - o * KP;
        Bs[o * STR_B + c] = (c < CIN) ? to_tf32(W[(obase + o) * CIN + c]) : 0.0f;
    }

    // ---- A stage 0 ----
    const int m = tid;
    float* Arow = As + m * STR_A;
    const float* Pb = nullptr;
    const float4* yrow = nullptr;
    if (MODE == 1) {
        const int bb = m0 >> 15;
        const int gi = gidx[m0 + m];
        Pb = points + ((size_t)bb * NN + gi) * 64;
        const float* Xb = xyz + ((size_t)bb * NN + gi) * 3;
        float4 t[10];
#pragma unroll
        for (int j = 0; j < 10; j++) t[j] = reinterpret_cast<const float4*>(Pb)[j];
        Arow[0] = to_tf32(__fsub_rn(Xb[0], sNew[m >> 5][0]));
        Arow[1] = to_tf32(__fsub_rn(Xb[1], sNew[m >> 5][1]));
        Arow[2] = to_tf32(__fsub_rn(Xb[2], sNew[m >> 5][2]));
#pragma unroll
        for (int c = 3; c < 40; c++) Arow[c] = to_tf32(((float*)t)[c - 3]);
    } else {
        yrow = reinterpret_cast<const float4*>(&yin[(size_t)(m0 + m) * 64]);
#pragma unroll
        for (int q = 0; q < 8; q++) {
            float4 v = yrow[q];
            int c = q * 4;
            v.x = to_tf32(fmaxf(fmaf(v.x, sSc[c + 0], sSh[c + 0]), 0.0f));
            v.y = to_tf32(fmaxf(fmaf(v.y, sSc[c + 1], sSh[c + 1]), 0.0f));
            v.z = to_tf32(fmaxf(fmaf(v.z, sSc[c + 2], sSh[c + 2]), 0.0f));
            v.w = to_tf32(fmaxf(fmaf(v.w, sSc[c + 3], sSh[c + 3]), 0.0f));
            *reinterpret_cast<float4*>(Arow + c) = v;
        }
    }
    __syncthreads();

    const int r = lane >> 2, cq = lane & 3;
    float acc[16][4];
#pragma unroll
    for (int i = 0; i < 16; i++) {
        acc[i][0] = 0.0f; acc[i][1] = 0.0f; acc[i][2] = 0.0f; acc[i][3] = 0.0f;
    }

    // ---- stage 0 MMA ----
#pragma unroll
    for (int ks = 0; ks < NK0; ks++) {
        const int kl = ks * 8;
        uint32_t a[2][4];
#pragma unroll
        for (int mt = 0; mt < 2; mt++) {
            const float* p = As + (w * 32 + mt * 16 + r) * STR_A + kl + cq;
            a[mt][0] = __float_as_uint(p[0]);
            a[mt][1] = __float_as_uint(p[8 * STR_A]);
            a[mt][2] = __float_as_uint(p[4]);
            a[mt][3] = __float_as_uint(p[8 * STR_A + 4]);
        }
#pragma unroll
        for (int nt = 0; nt < 8; nt++) {
            const float* q = Bs + (nt * 8 + r) * STR_B + kl + cq;
            uint32_t bfr[2];
            bfr[0] = __float_as_uint(q[0]);
            bfr[1] = __float_as_uint(q[4]);
            mma16n8k8(acc[nt], a[0], bfr);
            mma16n8k8(acc[8 + nt], a[1], bfr);
        }
    }
    __syncthreads();

    // ---- A stage 1 ----
    if (MODE == 1) {
        float4 t2[7];
#pragma unroll
        for (int j = 0; j < 7; j++) t2[j] = reinterpret_cast<const float4*>(Pb)[9 + j];
#pragma unroll
        for (int cc = 0; cc < 32; cc++)
            Arow[cc] = (cc < 27) ? to_tf32(((float*)t2)[cc + 1]) : 0.0f;
    } else {
#pragma unroll
        for (int q = 8; q < 16; q++) {
            float4 v = yrow[q];
            int c = q * 4;
            v.x = to_tf32(fmaxf(fmaf(v.x, sSc[c + 0], sSh[c + 0]), 0.0f));
            v.y = to_tf32(fmaxf(fmaf(v.y, sSc[c + 1], sSh[c + 1]), 0.0f));
            v.z = to_tf32(fmaxf(fmaf(v.z, sSc[c + 2], sSh[c + 2]), 0.0f));
            v.w = to_tf32(fmaxf(fmaf(v.w, sSc[c + 3], sSh[c + 3]), 0.0f));
            *reinterpret_cast<float4*>(Arow + (q - 8) * 4) = v;
        }
    }
    __syncthreads();

    // ---- stage 1 MMA ----
#pragma unroll
    for (int ks = 0; ks < NK1; ks++) {
        const int kl = ks * 8, kg = S0 + ks * 8;
        uint32_t a[2][4];
#pragma unroll
        for (int mt = 0; mt < 2; mt++) {
            const float* p = As + (w * 32 + mt * 16 + r) * STR_A + kl + cq;
            a[mt][0] = __float_as_uint(p[0]);
            a[mt][1] = __float_as_uint(p[8 * STR_A]);
            a[mt][2] = __float_as_uint(p[4]);
            a[mt][3] = __float_as_uint(p[8 * STR_A + 4]);
        }
#pragma unroll
        for (int nt = 0; nt < 8; nt++) {
            const float* q = Bs + (nt * 8 + r) * STR_B + kg + cq;
            uint32_t bfr[2];
            bfr[0] = __float_as_uint(q[0]);
            bfr[1] = __float_as_uint(q[4]);
            mma16n8k8(acc[nt], a[0], bfr);
            mma16n8k8(acc[8 + nt], a[1], bfr);
        }
    }
    __syncthreads();   // A/B smem dead; reuse as ys[128][65]

    // ---- epilogue: bias add, scatter to ys[m][o] ----
    float* ys = sm;
#pragma unroll
    for (int mt = 0; mt < 2; mt++) {
#pragma unroll
        for (int nt = 0; nt < 8; nt++) {
            const int row = w * 32 + mt * 16 + r;
            const int col = nt * 8 + 2 * cq;
            const float* c = acc[mt * 8 + nt];
            ys[row * 65 + col]           = c[0] + sBias[col];
            ys[row * 65 + col + 1]       = c[1] + sBias[col + 1];
            ys[(row + 8) * 65 + col]     = c[2] + sBias[col];
            ys[(row + 8) * 65 + col + 1] = c[3] + sBias[col + 1];
        }
    }
    __syncthreads();

    // block stats (deterministic order)
    {
        const int o = tid & 63, h = tid >> 6;
        float s = 0.0f, ss = 0.0f;
#pragma unroll 8
        for (int i = 0; i < 64; i++) {
            float v = ys[(h * 64 + i) * 65 + o];
            s += v; ss += v * v;
        }
        redS[h][o] = s; redQ[h][o] = ss;
    }
    __syncthreads();
    if (tid < 64) {
        part[blockIdx.x * 128 + tid] = redS[0][tid] + redS[1][tid];
        part[blockIdx.x * 128 + 64 + tid] = redQ[0][tid] + redQ[1][tid];
    }
    if (MODE == 3) {
        // per-query (32-row) raw max per channel -> mx[q][128]
        const int o = tid & 63, h = tid >> 6;
        const int q0 = m0 >> 5;
#pragma unroll
        for (int g = h; g < 4; g += 2) {
            float mxv = -1e30f;
#pragma unroll 8
            for (int i = 0; i < 32; i++)
                mxv = fmaxf(mxv, ys[(g * 32 + i) * 65 + o]);
            yout[(size_t)(q0 + g) * 128 + obase + o] = mxv;
        }
    } else {
        for (int e = tid; e < 8192; e += 128) {
            int mm = e >> 6, o = e & 63;
            yout[(size_t)(m0 + mm) * 64 + o] = ys[mm * 65 + o];
        }
    }
}

// ---------------- 4) BN stats reduction -> scale/shift (deterministic) ----------------
template <int NCH>
__global__ void __launch_bounds__(256) reduce_kernel(const float* __restrict__ part,
                                                     const float* __restrict__ pg,
                                                     const float* __restrict__ pbe,
                                                     float* __restrict__ scout,
                                                     float* __restrict__ shout,
                                                     int nrows) {
    const int ch = blockIdx.x;
    float s = 0.0f, ss = 0.0f;
    if (NCH == 64) {
        for (int rr = threadIdx.x; rr < nrows; rr += 256) {
            s += part[rr * 128 + ch];
            ss += part[rr * 128 + 64 + ch];
        }
    } else {
        const int p = ch >> 6, lc = ch & 63;
        const int half = nrows >> 1;
        for (int i = threadIdx.x; i < half; i += 256) {
            int rr = 2 * i + p;
            s += part[rr * 128 + lc];
            ss += part[rr * 128 + 64 + lc];
        }
    }
    __shared__ float as_[8], bs_[8];
#pragma unroll
    for (int off = 16; off; off >>= 1) {
        s += __shfl_down_sync(0xffffffffu, s, off);
        ss += __shfl_down_sync(0xffffffffu, ss, off);
    }
    const int lane = threadIdx.x & 31, wid = threadIdx.x >> 5;
    if (lane == 0) { as_[wid] = s; bs_[wid] = ss; }
    __syncthreads();
    if (threadIdx.x == 0) {
        float S = 0.0f, Q = 0.0f;
        for (int i = 0; i < 8; i++) { S += as_[i]; Q += bs_[i]; }
        float mean = S * INV_N;
        float var = Q * INV_N - mean * mean;
        float inv = rsqrtf(var + 1e-5f);
        float scv = pg[ch] * inv;
        scout[ch] = scv;
        shout[ch] = pbe[ch] - mean * scv;
    }
}

// ---------------- 5) final: BN3-affine + relu on per-query max, transpose ----------------
// grid = NB*32 blocks; block handles 32 queries x 128 channels.
__global__ void __launch_bounds__(256) final_kernel(const float* __restrict__ mx,
                                                    const float* __restrict__ sc3,
                                                    const float* __restrict__ sh3,
                                                    float* __restrict__ out) {
    __shared__ float t[32][129];
    const int blk = blockIdx.x;
    const int b = blk >> 5, s0 = (blk & 31) * 32;
    const int tid = threadIdx.x;
    for (int e = tid; e < 32 * 128; e += 256) {
        int q = e >> 7, o = e & 127;
        t[q][o] = mx[(size_t)(b * 1024 + s0 + q) * 128 + o];
    }
    __syncthreads();
    for (int e = tid; e < 128 * 32; e += 256) {
        int o = e >> 5, q = e & 31;
        float v = fmaxf(fmaf(t[q][o], sc3[o], sh3[o]), 0.0f);
        out[NEWXYZ_ELEMS + (size_t)(b * 128 + o) * 1024 + s0 + q] = v;
    }
}

// ---------------- launch ----------------
extern "C" void kernel_launch(void* const* d_in, const int* in_sizes, int n_in,
                              void* d_out, int out_size) {
    const float* xyz    = (const float*)d_in[0];
    const float* points = (const float*)d_in[1];
    const float* w1 = (const float*)d_in[2];
    const float* b1 = (const float*)d_in[3];
    const float* g1 = (const float*)d_in[4];
    const float* be1 = (const float*)d_in[5];
    const float* w2 = (const float*)d_in[6];
    const float* b2 = (const float*)d_in[7];
    const float* g2 = (const float*)d_in[8];
    const float* be2 = (const float*)d_in[9];
    const float* w3 = (const float*)d_in[10];
    const float* b3 = (const float*)d_in[11];
    const float* g3 = (const float*)d_in[12];
    const float* be3 = (const float*)d_in[13];
    float* out = (float*)d_out;

    float *y1, *y2, *mx, *p1, *p2, *p3;
    float *sc1, *sh1, *sc2, *sh2, *sc3, *sh3;
    int* idx;
    cudaGetSymbolAddress((void**)&y1, g_y1);
    cudaGetSymbolAddress((void**)&y2, g_y2);
    cudaGetSymbolAddress((void**)&mx, g_mx);
    cudaGetSymbolAddress((void**)&idx, g_idx);
    cudaGetSymbolAddress((void**)&p1, g_part1);
    cudaGetSymbolAddress((void**)&p2, g_part2);
    cudaGetSymbolAddress((void**)&p3, g_part3);
    cudaGetSymbolAddress((void**)&sc1, g_sc1);
    cudaGetSymbolAddress((void**)&sh1, g_sh1);
    cudaGetSymbolAddress((void**)&sc2, g_sc2);
    cudaGetSymbolAddress((void**)&sh2, g_sh2);
    cudaGetSymbolAddress((void**)&sc3, g_sc3);
    cudaGetSymbolAddress((void**)&sh3, g_sh3);

    const int smemF = NN * 3 * 4;                      // 98304 (fps)
    const int smem1 = (128 * 44 + 64 * 76) * 4;        // 41984
    const int smem2 = (128 * 36 + 64 * 68) * 4;        // 35840
    cudaFuncSetAttribute(fps_kernel, cudaFuncAttributeMaxDynamicSharedMemorySize, smemF);
    cudaFuncSetAttribute(mma_kernel<1>, cudaFuncAttributeMaxDynamicSharedMemorySize, smem1);
    cudaFuncSetAttribute(mma_kernel<2>, cudaFuncAttributeMaxDynamicSharedMemorySize, smem2);
    cudaFuncSetAttribute(mma_kernel<3>, cudaFuncAttributeMaxDynamicSharedMemorySize, smem2);

    // 1) FPS -> new_xyz (first 49152 elems of out)
    fps_kernel<<<NB, 512, smemF>>>(xyz, out);
    // 2) ball query -> g_idx
    ball_kernel<<<(NB * NPOINT * 32) / 256, 256>>>(xyz, out, idx);
    // 3) layer1 (gather 67ch -> 64)
    mma_kernel<1><<<M_TOTAL / 128, 128, smem1>>>(
        xyz, points, out, idx, nullptr, nullptr, nullptr, w1, b1, y1, p1);
    reduce_kernel<64><<<64, 256>>>(p1, g1, be1, sc1, sh1, 4096);
    // 4) layer2 (BN1+relu fused on load)
    mma_kernel<2><<<M_TOTAL / 128, 128, smem2>>>(
        nullptr, nullptr, nullptr, nullptr, y1, sc1, sh1, w2, b2, y2, p2);
    reduce_kernel<64><<<64, 256>>>(p2, g2, be2, sc2, sh2, 4096);
    // 5) layer3 (BN2+relu fused on load); emits per-query raw max + stats
    mma_kernel<3><<<2 * (M_TOTAL / 128), 128, smem2>>>(
        nullptr, nullptr, nullptr, nullptr, y2, sc2, sh2, w3, b3, mx, p3);
    reduce_kernel<128><<<128, 256>>>(p3, g3, be3, sc3, sh3, 8192);
    // 6) BN3-affine + relu on max, transposed write
    final_kernel<<<NB * 32, 256>>>(mx, sc3, sh3, out);
}

// round 12
// speedup vs baseline: 1.5610x; 1.5610x over previous
#include <cuda_runtime.h>
#include <cstdint>

typedef unsigned long long ull;

// Problem constants
constexpr int NB = 16, NN = 8192, NPOINT = 1024, NSAMPLE = 32;
constexpr int M_TOTAL = NB * NPOINT * NSAMPLE;       // 524288 positions
constexpr float INV_N = 1.0f / (float)M_TOTAL;       // 2^-19, exact
constexpr int NEWXYZ_ELEMS = NB * NPOINT * 3;        // 49152

// -------- scratch (device globals; no allocation allowed) --------
__device__ float g_y1[(size_t)M_TOTAL * 64];
__device__ float g_y2[(size_t)M_TOTAL * 64];
__device__ float g_mx[(size_t)NB * NPOINT * 128];    // per-query raw max (pre-BN3)
__device__ int   g_idx[M_TOTAL];
__device__ float g_part1[4096 * 128];
__device__ float g_part2[4096 * 128];
__device__ float g_part3[8192 * 128];
__device__ float g_sc1[64],  g_sh1[64];
__device__ float g_sc2[64],  g_sh2[64];
__device__ float g_sc3[128], g_sh3[128];

// ---------------- helpers ----------------
__device__ __forceinline__ float to_tf32(float x) {
    unsigned u;
    asm("cvt.rna.tf32.f32 %0, %1;" : "=r"(u) : "f"(x));
    return __uint_as_float(u);
}
__device__ __forceinline__ float sqdist3(float dx, float dy, float dz) {
    return fmaf(dz, dz, fmaf(dy, dy, __fmul_rn(dx, dx)));
}
// m16n8k8 tf32 HMMA (PTX-portable on compute_103; runs on tensor pipes)
__device__ __forceinline__ void mma16n8k8(float* d, const uint32_t* a,
                                          const uint32_t* b) {
    asm volatile(
        "mma.sync.aligned.m16n8k8.row.col.f32.tf32.tf32.f32 "
        "{%0,%1,%2,%3}, {%4,%5,%6,%7}, {%8,%9}, {%0,%1,%2,%3};"
        : "+f"(d[0]), "+f"(d[1]), "+f"(d[2]), "+f"(d[3])
        : "r"(a[0]), "r"(a[1]), "r"(a[2]), "r"(a[3]), "r"(b[0]), "r"(b[1]));
}

// ---------------- 1) farthest point sampling ----------------
// One block per batch; 512 threads x 16 points in registers.
// xyz mirrored in smem; one __syncthreads per iteration; index found by
// leader-lane rescan (first-index tie-break preserved).
__global__ void __launch_bounds__(512) fps_kernel(const float* __restrict__ xyz,
                                                  float* __restrict__ newxyz) {
    extern __shared__ float sx[];   // [NN*3]
    const int b = blockIdx.x, tid = threadIdx.x;
    const float* X = xyz + (size_t)b * NN * 3;
    float px[16], py[16], pz[16], dd[16];
#pragma unroll
    for (int j = 0; j < 16; j++) {
        int p = tid * 16 + j;
        px[j] = X[p * 3 + 0]; py[j] = X[p * 3 + 1]; pz[j] = X[p * 3 + 2];
        dd[j] = 1e10f;
    }
    for (int e = tid; e < NN * 3; e += 512) sx[e] = X[e];

    __shared__ int swv[2][16];
    __shared__ int swi[2][16];
    __syncthreads();

    float cx = sx[0], cy = sx[1], cz = sx[2];
    float* outb = newxyz + (size_t)b * NPOINT * 3;
    const int lane = tid & 31, wid = tid >> 5;
    int buf = 0;

    for (int it = 0; it < NPOINT; ++it) {
        if (tid == 0) {
            outb[it * 3 + 0] = cx;
            outb[it * 3 + 1] = cy;
            outb[it * 3 + 2] = cz;
        }
        float best = -1.0f;
#pragma unroll
        for (int j = 0; j < 16; j++) {
            float dx = __fsub_rn(px[j], cx);
            float dy = __fsub_rn(py[j], cy);
            float dz = __fsub_rn(pz[j], cz);
            float d = sqdist3(dx, dy, dz);
            float nd = fminf(dd[j], d);
            dd[j] = nd;
            best = fmaxf(best, nd);
        }
        // warp argmax: nonneg float bits compare as ints
        int vb = __float_as_int(best);
        int wmax = __reduce_max_sync(0xffffffffu, vb);
        unsigned msk = __ballot_sync(0xffffffffu, vb == wmax);
        int ldr = __ffs(msk) - 1;               // lowest lane = lowest point idx
        int widx = 0;
        if (lane == ldr) {
#pragma unroll
            for (int j = 15; j >= 0; j--)       // descending -> first j wins
                if (__float_as_int(dd[j]) == wmax) widx = tid * 16 + j;
        }
        widx = __shfl_sync(0xffffffffu, widx, ldr);
        if (lane == 0) { swv[buf][wid] = wmax; swi[buf][wid] = widx; }
        __syncthreads();
        // all warps redundantly reduce the 16 warp results
        int l = lane & 15;
        int v2 = swv[buf][l], i2 = swi[buf][l];
        int m2 = __reduce_max_sync(0xffffffffu, v2);
        unsigned mk2 = __ballot_sync(0xffffffffu, v2 == m2);
        int l2 = __ffs(mk2) - 1;                // lands in 0..15 (mirrored halves)
        int f = __shfl_sync(0xffffffffu, i2, l2);
        cx = sx[f * 3 + 0]; cy = sx[f * 3 + 1]; cz = sx[f * 3 + 2];
        buf ^= 1;
    }
}

// ---------------- 2) ball query ----------------
__global__ void __launch_bounds__(256) ball_kernel(const float* __restrict__ xyz,
                                                   const float* __restrict__ newxyz,
                                                   int* __restrict__ gidx) {
    const int gwarp = (blockIdx.x * blockDim.x + threadIdx.x) >> 5;
    const int lane = threadIdx.x & 31;
    if (gwarp >= NB * NPOINT) return;
    const int b = gwarp >> 10;
    const float R2 = (float)(0.2 * 0.2);

    const float cx = newxyz[gwarp * 3 + 0];
    const float cy = newxyz[gwarp * 3 + 1];
    const float cz = newxyz[gwarp * 3 + 2];
    const float* X = xyz + (size_t)b * NN * 3;
    int* out = gidx + (size_t)gwarp * NSAMPLE;

    int cnt = 0;
    int first = NN - 1;
    for (int base = 0; base < NN; base += 32) {
        int j = base + lane;
        float dx = __fsub_rn(cx, X[j * 3 + 0]);
        float dy = __fsub_rn(cy, X[j * 3 + 1]);
        float dz = __fsub_rn(cz, X[j * 3 + 2]);
        float sq = sqdist3(dx, dy, dz);
        bool in = !(sq > R2);
        unsigned mask = __ballot_sync(0xffffffffu, in);
        if (mask) {
            if (cnt == 0) first = base + __ffs(mask) - 1;
            if (in) {
                int slot = cnt + __popc(mask & ((1u << lane) - 1u));
                if (slot < NSAMPLE) out[slot] = j;
            }
            cnt += __popc(mask);
            if (cnt >= NSAMPLE) break;
        }
    }
    if (cnt < NSAMPLE && lane >= cnt) out[lane] = first;
}

// ---------------- 3) HMMA tf32 GEMM per layer (K-split, 2 stages) ----------------
// Block = 128 threads (4 warps), tile = 128 positions x 64 outputs.
// Epilogue: BN stats + (MODE3) per-query max computed from accumulator
// registers via shfl.xor trees (no serial smem scans).
// MODE 1: gather 67ch -> y1.  MODE 2: y1 -> y2.
// MODE 3: y2 -> per-query max only (no y3; BN3-affine+relu commute with max).
template <int MODE>
__global__ void __launch_bounds__(128) mma_kernel(
    const float* __restrict__ xyz, const float* __restrict__ points,
    const float* __restrict__ newxyz, const int* __restrict__ gidx,
    const float* __restrict__ yin,
    const float* __restrict__ scin, const float* __restrict__ shin,
    const float* __restrict__ W, const float* __restrict__ bias,
    float* __restrict__ yout, float* __restrict__ part) {
    constexpr int CIN = (MODE == 1) ? 67 : 64;
    constexpr int KP  = (MODE == 1) ? 72 : 64;
    constexpr int S0  = (MODE == 1) ? 40 : 32;   // stage-0 cols
    constexpr int S1  = KP - S0;                 // 32
    constexpr int STR_A = S0 + 4;                // 44 / 36
    constexpr int STR_B = KP + 4;                // 76 / 68
    constexpr int NK0 = S0 / 8, NK1 = S1 / 8;

    extern __shared__ float sm[];
    float* As = sm;                    // [128][STR_A]
    float* Bs = sm + 128 * STR_A;      // [64][STR_B]
    __shared__ float sSc[64], sSh[64], sBias[64];
    __shared__ float sNew[4][3];
    __shared__ float wS[4][64], wQ[4][64];

    const int tid = threadIdx.x;
    const int lane = tid & 31, w = tid >> 5;
    int m_tile, obase;
    if (MODE == 3) { m_tile = blockIdx.x >> 1; obase = (blockIdx.x & 1) << 6; }
    else           { m_tile = blockIdx.x;      obase = 0; }
    const int m0 = m_tile * 128;

    if (tid < 64) sBias[tid] = bias[obase + tid];
    if (MODE == 1) {
        if (tid < 12) ((float*)sNew)[tid] = newxyz[(m0 >> 5) * 3 + tid];
    } else {
        if (tid >= 64) { sSc[tid - 64] = scin[tid - 64]; sSh[tid - 64] = shin[tid - 64]; }
    }
    __syncthreads();

    // ---- B (weights, full K) ----
    for (int e = tid; e < 64 * KP; e += 128) {
        int o = e / KP, c = e - o * KP;
        Bs[o * STR_B + c] = (c < CIN) ? to_tf32(W[(obase + o) * CIN + c]) : 0.0f;
    }

    // ---- A stage 0 ----
    const int m = tid;
    float* Arow = As + m * STR_A;
    const float* Pb = nullptr;
    const float4* yrow = nullptr;
    if (MODE == 1) {
        const int bb = m0 >> 15;
        const int gi = gidx[m0 + m];
        Pb = points + ((size_t)bb * NN + gi) * 64;
        const float* Xb = xyz + ((size_t)bb * NN + gi) * 3;
        float4 t[10];
#pragma unroll
        for (int j = 0; j < 10; j++) t[j] = reinterpret_cast<const float4*>(Pb)[j];
        Arow[0] = to_tf32(__fsub_rn(Xb[0], sNew[m >> 5][0]));
        Arow[1] = to_tf32(__fsub_rn(Xb[1], sNew[m >> 5][1]));
        Arow[2] = to_tf32(__fsub_rn(Xb[2], sNew[m >> 5][2]));
#pragma unroll
        for (int c = 3; c < 40; c++) Arow[c] = to_tf32(((float*)t)[c - 3]);
    } else {
        yrow = reinterpret_cast<const float4*>(&yin[(size_t)(m0 + m) * 64]);
#pragma unroll
        for (int q = 0; q < 8; q++) {
            float4 v = yrow[q];
            int c = q * 4;
            v.x = to_tf32(fmaxf(fmaf(v.x, sSc[c + 0], sSh[c + 0]), 0.0f));
            v.y = to_tf32(fmaxf(fmaf(v.y, sSc[c + 1], sSh[c + 1]), 0.0f));
            v.z = to_tf32(fmaxf(fmaf(v.z, sSc[c + 2], sSh[c + 2]), 0.0f));
            v.w = to_tf32(fmaxf(fmaf(v.w, sSc[c + 3], sSh[c + 3]), 0.0f));
            *reinterpret_cast<float4*>(Arow + c) = v;
        }
    }
    __syncthreads();

    const int r = lane >> 2, cq = lane & 3;
    float acc[16][4];
#pragma unroll
    for (int i = 0; i < 16; i++) {
        acc[i][0] = 0.0f; acc[i][1] = 0.0f; acc[i][2] = 0.0f; acc[i][3] = 0.0f;
    }

    // ---- stage 0 MMA ----
#pragma unroll
    for (int ks = 0; ks < NK0; ks++) {
        const int kl = ks * 8;
        uint32_t a[2][4];
#pragma unroll
        for (int mt = 0; mt < 2; mt++) {
            const float* p = As + (w * 32 + mt * 16 + r) * STR_A + kl + cq;
            a[mt][0] = __float_as_uint(p[0]);
            a[mt][1] = __float_as_uint(p[8 * STR_A]);
            a[mt][2] = __float_as_uint(p[4]);
            a[mt][3] = __float_as_uint(p[8 * STR_A + 4]);
        }
#pragma unroll
        for (int nt = 0; nt < 8; nt++) {
            const float* q = Bs + (nt * 8 + r) * STR_B + kl + cq;
            uint32_t bfr[2];
            bfr[0] = __float_as_uint(q[0]);
            bfr[1] = __float_as_uint(q[4]);
            mma16n8k8(acc[nt], a[0], bfr);
            mma16n8k8(acc[8 + nt], a[1], bfr);
        }
    }
    __syncthreads();

    // ---- A stage 1 ----
    if (MODE == 1) {
        float4 t2[7];
#pragma unroll
        for (int j = 0; j < 7; j++) t2[j] = reinterpret_cast<const float4*>(Pb)[9 + j];
#pragma unroll
        for (int cc = 0; cc < 32; cc++)
            Arow[cc] = (cc < 27) ? to_tf32(((float*)t2)[cc + 1]) : 0.0f;
    } else {
#pragma unroll
        for (int q = 8; q < 16; q++) {
            float4 v = yrow[q];
            int c = q * 4;
            v.x = to_tf32(fmaxf(fmaf(v.x, sSc[c + 0], sSh[c + 0]), 0.0f));
            v.y = to_tf32(fmaxf(fmaf(v.y, sSc[c + 1], sSh[c + 1]), 0.0f));
            v.z = to_tf32(fmaxf(fmaf(v.z, sSc[c + 2], sSh[c + 2]), 0.0f));
            v.w = to_tf32(fmaxf(fmaf(v.w, sSc[c + 3], sSh[c + 3]), 0.0f));
            *reinterpret_cast<float4*>(Arow + (q - 8) * 4) = v;
        }
    }
    __syncthreads();

    // ---- stage 1 MMA ----
#pragma unroll
    for (int ks = 0; ks < NK1; ks++) {
        const int kl = ks * 8, kg = S0 + ks * 8;
        uint32_t a[2][4];
#pragma unroll
        for (int mt = 0; mt < 2; mt++) {
            const float* p = As + (w * 32 + mt * 16 + r) * STR_A + kl + cq;
            a[mt][0] = __float_as_uint(p[0]);
            a[mt][1] = __float_as_uint(p[8 * STR_A]);
            a[mt][2] = __float_as_uint(p[4]);
            a[mt][3] = __float_as_uint(p[8 * STR_A + 4]);
        }
#pragma unroll
        for (int nt = 0; nt < 8; nt++) {
            const float* q = Bs + (nt * 8 + r) * STR_B + kg + cq;
            uint32_t bfr[2];
            bfr[0] = __float_as_uint(q[0]);
            bfr[1] = __float_as_uint(q[4]);
            mma16n8k8(acc[nt], a[0], bfr);
            mma16n8k8(acc[8 + nt], a[1], bfr);
        }
    }

    // ---- register epilogue: bias + warp-level stats (and MODE3 max) ----
    // Warp w owns rows w*32..w*32+31; thread holds rows {r, r+8, r+16, r+24}
    // for cols {nt*8+2cq, +1}. shfl.xor over lane bits 2..4 reduces over r.
#pragma unroll
    for (int nt = 0; nt < 8; nt++) {
        const int col = nt * 8 + 2 * cq;
        const float b0 = sBias[col], b1 = sBias[col + 1];
        float v00 = acc[nt][0] + b0,     v01 = acc[nt][1] + b1;
        float v02 = acc[nt][2] + b0,     v03 = acc[nt][3] + b1;
        float v10 = acc[8 + nt][0] + b0, v11 = acc[8 + nt][1] + b1;
        float v12 = acc[8 + nt][2] + b0, v13 = acc[8 + nt][3] + b1;
        // write back biased values for the y-store path (MODE 1/2)
        acc[nt][0] = v00; acc[nt][1] = v01; acc[nt][2] = v02; acc[nt][3] = v03;
        acc[8 + nt][0] = v10; acc[8 + nt][1] = v11;
        acc[8 + nt][2] = v12; acc[8 + nt][3] = v13;

        float s0 = (v00 + v02) + (v10 + v12);
        float s1 = (v01 + v03) + (v11 + v13);
        float q0 = fmaf(v00, v00, v02 * v02) + fmaf(v10, v10, v12 * v12);
        float q1 = fmaf(v01, v01, v03 * v03) + fmaf(v11, v11, v13 * v13);
        float mx0 = 0.0f, mx1 = 0.0f;
        if (MODE == 3) {
            mx0 = fmaxf(fmaxf(v00, v02), fmaxf(v10, v12));
            mx1 = fmaxf(fmaxf(v01, v03), fmaxf(v11, v13));
        }
#pragma unroll
        for (int off = 4; off <= 16; off <<= 1) {
            s0 += __shfl_xor_sync(0xffffffffu, s0, off);
            s1 += __shfl_xor_sync(0xffffffffu, s1, off);
            q0 += __shfl_xor_sync(0xffffffffu, q0, off);
            q1 += __shfl_xor_sync(0xffffffffu, q1, off);
            if (MODE == 3) {
                mx0 = fmaxf(mx0, __shfl_xor_sync(0xffffffffu, mx0, off));
                mx1 = fmaxf(mx1, __shfl_xor_sync(0xffffffffu, mx1, off));
            }
        }
        if (r == 0) {
            wS[w][col] = s0; wS[w][col + 1] = s1;
            wQ[w][col] = q0; wQ[w][col + 1] = q1;
            if (MODE == 3) {
                // warp w = query (m0>>5)+w
                float* dst = yout + (size_t)((m0 >> 5) + w) * 128 + obase + col;
                dst[0] = mx0; dst[1] = mx1;
            }
        }
    }
    __syncthreads();
    if (tid < 64) {
        part[blockIdx.x * 128 + tid] =
            (wS[0][tid] + wS[1][tid]) + (wS[2][tid] + wS[3][tid]);
        part[blockIdx.x * 128 + 64 + tid] =
            (wQ[0][tid] + wQ[1][tid]) + (wQ[2][tid] + wQ[3][tid]);
    }

    if (MODE != 3) {
        // scatter biased acc -> ys[128][65] (smem reuse), then coalesced y write
        float* ys = sm;
#pragma unroll
        for (int mt = 0; mt < 2; mt++) {
#pragma unroll
            for (int nt = 0; nt < 8; nt++) {
                const int row = w * 32 + mt * 16 + r;
                const int col = nt * 8 + 2 * cq;
                const float* c = acc[mt * 8 + nt];
                ys[row * 65 + col]           = c[0];
                ys[row * 65 + col + 1]       = c[1];
                ys[(row + 8) * 65 + col]     = c[2];
                ys[(row + 8) * 65 + col + 1] = c[3];
            }
        }
        __syncthreads();
        for (int e = tid; e < 8192; e += 128) {
            int mm = e >> 6, o = e & 63;
            yout[(size_t)(m0 + mm) * 64 + o] = ys[mm * 65 + o];
        }
    }
}

// ---------------- 4) BN stats reduction -> scale/shift (deterministic) ----------------
template <int NCH>
__global__ void __launch_bounds__(256) reduce_kernel(const float* __restrict__ part,
                                                     const float* __restrict__ pg,
                                                     const float* __restrict__ pbe,
                                                     float* __restrict__ scout,
                                                     float* __restrict__ shout,
                                                     int nrows) {
    const int ch = blockIdx.x;
    float s = 0.0f, ss = 0.0f;
    if (NCH == 64) {
        for (int rr = threadIdx.x; rr < nrows; rr += 256) {
            s += part[rr * 128 + ch];
            ss += part[rr * 128 + 64 + ch];
        }
    } else {
        const int p = ch >> 6, lc = ch & 63;
        const int half = nrows >> 1;
        for (int i = threadIdx.x; i < half; i += 256) {
            int rr = 2 * i + p;
            s += part[rr * 128 + lc];
            ss += part[rr * 128 + 64 + lc];
        }
    }
    __shared__ float as_[8], bs_[8];
#pragma unroll
    for (int off = 16; off; off >>= 1) {
        s += __shfl_down_sync(0xffffffffu, s, off);
        ss += __shfl_down_sync(0xffffffffu, ss, off);
    }
    const int lane = threadIdx.x & 31, wid = threadIdx.x >> 5;
    if (lane == 0) { as_[wid] = s; bs_[wid] = ss; }
    __syncthreads();
    if (threadIdx.x == 0) {
        float S = 0.0f, Q = 0.0f;
        for (int i = 0; i < 8; i++) { S += as_[i]; Q += bs_[i]; }
        float mean = S * INV_N;
        float var = Q * INV_N - mean * mean;
        float inv = rsqrtf(var + 1e-5f);
        float scv = pg[ch] * inv;
        scout[ch] = scv;
        shout[ch] = pbe[ch] - mean * scv;
    }
}

// ---------------- 5) final: BN3-affine + relu on per-query max, transpose ----------------
// grid = NB*32 blocks; block handles 32 queries x 128 channels.
__global__ void __launch_bounds__(256) final_kernel(const float* __restrict__ mx,
                                                    const float* __restrict__ sc3,
                                                    const float* __restrict__ sh3,
                                                    float* __restrict__ out) {
    __shared__ float t[32][129];
    const int blk = blockIdx.x;
    const int b = blk >> 5, s0 = (blk & 31) * 32;
    const int tid = threadIdx.x;
    for (int e = tid; e < 32 * 128; e += 256) {
        int q = e >> 7, o = e & 127;
        t[q][o] = mx[(size_t)(b * 1024 + s0 + q) * 128 + o];
    }
    __syncthreads();
    for (int e = tid; e < 128 * 32; e += 256) {
        int o = e >> 5, q = e & 31;
        float v = fmaxf(fmaf(t[q][o], sc3[o], sh3[o]), 0.0f);
        out[NEWXYZ_ELEMS + (size_t)(b * 128 + o) * 1024 + s0 + q] = v;
    }
}

// ---------------- launch ----------------
extern "C" void kernel_launch(void* const* d_in, const int* in_sizes, int n_in,
                              void* d_out, int out_size) {
    const float* xyz    = (const float*)d_in[0];
    const float* points = (const float*)d_in[1];
    const float* w1 = (const float*)d_in[2];
    const float* b1 = (const float*)d_in[3];
    const float* g1 = (const float*)d_in[4];
    const float* be1 = (const float*)d_in[5];
    const float* w2 = (const float*)d_in[6];
    const float* b2 = (const float*)d_in[7];
    const float* g2 = (const float*)d_in[8];
    const float* be2 = (const float*)d_in[9];
    const float* w3 = (const float*)d_in[10];
    const float* b3 = (const float*)d_in[11];
    const float* g3 = (const float*)d_in[12];
    const float* be3 = (const float*)d_in[13];
    float* out = (float*)d_out;

    float *y1, *y2, *mx, *p1, *p2, *p3;
    float *sc1, *sh1, *sc2, *sh2, *sc3, *sh3;
    int* idx;
    cudaGetSymbolAddress((void**)&y1, g_y1);
    cudaGetSymbolAddress((void**)&y2, g_y2);
    cudaGetSymbolAddress((void**)&mx, g_mx);
    cudaGetSymbolAddress((void**)&idx, g_idx);
    cudaGetSymbolAddress((void**)&p1, g_part1);
    cudaGetSymbolAddress((void**)&p2, g_part2);
    cudaGetSymbolAddress((void**)&p3, g_part3);
    cudaGetSymbolAddress((void**)&sc1, g_sc1);
    cudaGetSymbolAddress((void**)&sh1, g_sh1);
    cudaGetSymbolAddress((void**)&sc2, g_sc2);
    cudaGetSymbolAddress((void**)&sh2, g_sh2);
    cudaGetSymbolAddress((void**)&sc3, g_sc3);
    cudaGetSymbolAddress((void**)&sh3, g_sh3);

    const int smemF = NN * 3 * 4;                      // 98304 (fps)
    const int smem1 = (128 * 44 + 64 * 76) * 4;        // 41984
    const int smem2 = (128 * 36 + 64 * 68) * 4;        // 35840
    cudaFuncSetAttribute(fps_kernel, cudaFuncAttributeMaxDynamicSharedMemorySize, smemF);
    cudaFuncSetAttribute(mma_kernel<1>, cudaFuncAttributeMaxDynamicSharedMemorySize, smem1);
    cudaFuncSetAttribute(mma_kernel<2>, cudaFuncAttributeMaxDynamicSharedMemorySize, smem2);
    cudaFuncSetAttribute(mma_kernel<3>, cudaFuncAttributeMaxDynamicSharedMemorySize, smem2);

    // 1) FPS -> new_xyz (first 49152 elems of out)
    fps_kernel<<<NB, 512, smemF>>>(xyz, out);
    // 2) ball query -> g_idx
    ball_kernel<<<(NB * NPOINT * 32) / 256, 256>>>(xyz, out, idx);
    // 3) layer1 (gather 67ch -> 64)
    mma_kernel<1><<<M_TOTAL / 128, 128, smem1>>>(
        xyz, points, out, idx, nullptr, nullptr, nullptr, w1, b1, y1, p1);
    reduce_kernel<64><<<64, 256>>>(p1, g1, be1, sc1, sh1, 4096);
    // 4) layer2 (BN1+relu fused on load)
    mma_kernel<2><<<M_TOTAL / 128, 128, smem2>>>(
        nullptr, nullptr, nullptr, nullptr, y1, sc1, sh1, w2, b2, y2, p2);
    reduce_kernel<64><<<64, 256>>>(p2, g2, be2, sc2, sh2, 4096);
    // 5) layer3 (BN2+relu fused on load); emits per-query raw max + stats
    mma_kernel<3><<<2 * (M_TOTAL / 128), 128, smem2>>>(
        nullptr, nullptr, nullptr, nullptr, y2, sc2, sh2, w3, b3, mx, p3);
    reduce_kernel<128><<<128, 256>>>(p3, g3, be3, sc3, sh3, 8192);
    // 6) BN3-affine + relu on max, transposed write
    final_kernel<<<NB * 32, 256>>>(mx, sc3, sh3, out);
}

// round 13
// speedup vs baseline: 1.6053x; 1.0283x over previous
#include <cuda_runtime.h>
#include <cstdint>

typedef unsigned long long ull;

// Problem constants
constexpr int NB = 16, NN = 8192, NPOINT = 1024, NSAMPLE = 32;
constexpr int M_TOTAL = NB * NPOINT * NSAMPLE;       // 524288 positions
constexpr float INV_N = 1.0f / (float)M_TOTAL;       // 2^-19, exact
constexpr int NEWXYZ_ELEMS = NB * NPOINT * 3;        // 49152

// -------- scratch (device globals; no allocation allowed) --------
__device__ float g_y1[(size_t)M_TOTAL * 64];
__device__ float g_y2[(size_t)M_TOTAL * 64];
__device__ float g_mx[(size_t)NB * NPOINT * 128];    // per-query raw max (pre-BN3)
__device__ int   g_idx[M_TOTAL];
__device__ float g_part1[4096 * 128];
__device__ float g_part2[4096 * 128];
__device__ float g_part3[8192 * 128];
__device__ float g_sc1[64],  g_sh1[64];
__device__ float g_sc2[64],  g_sh2[64];
__device__ float g_sc3[128], g_sh3[128];

// ---------------- helpers ----------------
__device__ __forceinline__ float to_tf32(float x) {
    unsigned u;
    asm("cvt.rna.tf32.f32 %0, %1;" : "=r"(u) : "f"(x));
    return __uint_as_float(u);
}
__device__ __forceinline__ float sqdist3(float dx, float dy, float dz) {
    return fmaf(dz, dz, fmaf(dy, dy, __fmul_rn(dx, dx)));
}
// packed f32x2 ops (sm_100+; lane-wise identical to scalar RN ops)
__device__ __forceinline__ ull pack2(float lo, float hi) {
    ull r;
    asm("mov.b64 %0, {%1, %2};" : "=l"(r) : "f"(lo), "f"(hi));
    return r;
}
__device__ __forceinline__ void unpack2i(ull v, int& lo, int& hi) {
    asm("mov.b64 {%0, %1}, %2;" : "=r"(lo), "=r"(hi) : "l"(v));
}
__device__ __forceinline__ ull add2(ull a, ull b) {
    ull r;
    asm("add.rn.f32x2 %0, %1, %2;" : "=l"(r) : "l"(a), "l"(b));
    return r;
}
__device__ __forceinline__ ull mul2(ull a, ull b) {
    ull r;
    asm("mul.rn.f32x2 %0, %1, %2;" : "=l"(r) : "l"(a), "l"(b));
    return r;
}
__device__ __forceinline__ void fma2(ull& d, ull a, ull b) {
    asm("fma.rn.f32x2 %0, %1, %2, %0;" : "+l"(d) : "l"(a), "l"(b));
}
// m16n8k8 tf32 HMMA (PTX-portable on compute_103; runs on tensor pipes)
__device__ __forceinline__ void mma16n8k8(float* d, const uint32_t* a,
                                          const uint32_t* b) {
    asm volatile(
        "mma.sync.aligned.m16n8k8.row.col.f32.tf32.tf32.f32 "
        "{%0,%1,%2,%3}, {%4,%5,%6,%7}, {%8,%9}, {%0,%1,%2,%3};"
        : "+f"(d[0]), "+f"(d[1]), "+f"(d[2]), "+f"(d[3])
        : "r"(a[0]), "r"(a[1]), "r"(a[2]), "r"(a[3]), "r"(b[0]), "r"(b[1]));
}

// ---------------- 1) farthest point sampling ----------------
// One block per batch; 512 threads x 16 points (8 f32x2 pairs) in registers.
// Distance chain in packed f32x2 (fma pipe), min/argmax as integer ops (alu
// pipe) — both pipes overlap. Bit-identical arithmetic to the scalar version:
// add.rn.f32x2(p, -c) == __fsub_rn(p, c); mul->fma->fma chain order unchanged;
// nonneg float bits are order-isomorphic to ints.
__global__ void __launch_bounds__(512) fps_kernel(const float* __restrict__ xyz,
                                                  float* __restrict__ newxyz) {
    extern __shared__ float sx[];   // [NN*3]
    const int b = blockIdx.x, tid = threadIdx.x;
    const float* X = xyz + (size_t)b * NN * 3;
    ull pxp[8], pyp[8], pzp[8];
    int dd[16];
#pragma unroll
    for (int j = 0; j < 8; j++) {
        int p = tid * 16 + 2 * j;
        pxp[j] = pack2(X[p * 3 + 0], X[p * 3 + 3]);
        pyp[j] = pack2(X[p * 3 + 1], X[p * 3 + 4]);
        pzp[j] = pack2(X[p * 3 + 2], X[p * 3 + 5]);
        dd[2 * j] = __float_as_int(1e10f);
        dd[2 * j + 1] = __float_as_int(1e10f);
    }
    for (int e = tid; e < NN * 3; e += 512) sx[e] = X[e];

    __shared__ int swv[2][16];
    __shared__ int swi[2][16];
    __syncthreads();

    float cx = sx[0], cy = sx[1], cz = sx[2];
    float* outb = newxyz + (size_t)b * NPOINT * 3;
    const int lane = tid & 31, wid = tid >> 5;
    int buf = 0;

    for (int it = 0; it < NPOINT; ++it) {
        if (tid == 0) {
            outb[it * 3 + 0] = cx;
            outb[it * 3 + 1] = cy;
            outb[it * 3 + 2] = cz;
        }
        const ull ncx = pack2(-cx, -cx);
        const ull ncy = pack2(-cy, -cy);
        const ull ncz = pack2(-cz, -cz);
        int best = 0x80000000;
#pragma unroll
        for (int j = 0; j < 8; j++) {
            ull dx = add2(pxp[j], ncx);
            ull dy = add2(pyp[j], ncy);
            ull dz = add2(pzp[j], ncz);
            ull t = mul2(dx, dx);
            fma2(t, dy, dy);
            fma2(t, dz, dz);
            int lo, hi;
            unpack2i(t, lo, hi);
            int n0 = min(dd[2 * j], lo);
            int n1 = min(dd[2 * j + 1], hi);
            dd[2 * j] = n0; dd[2 * j + 1] = n1;
            best = max(best, max(n0, n1));
        }
        // warp argmax on int-ordered distances; ballot -> min-index tie
        int wmax = __reduce_max_sync(0xffffffffu, best);
        unsigned msk = __ballot_sync(0xffffffffu, best == wmax);
        int ldr = __ffs(msk) - 1;               // lowest lane = lowest point idx
        int widx = 0;
        if (lane == ldr) {
#pragma unroll
            for (int j = 15; j >= 0; j--)       // descending -> first j wins
                if (dd[j] == wmax) widx = tid * 16 + j;
        }
        widx = __shfl_sync(0xffffffffu, widx, ldr);
        if (lane == 0) { swv[buf][wid] = wmax; swi[buf][wid] = widx; }
        __syncthreads();
        // all warps redundantly reduce the 16 warp results
        int l = lane & 15;
        int v2 = swv[buf][l], i2 = swi[buf][l];
        int m2 = __reduce_max_sync(0xffffffffu, v2);
        unsigned mk2 = __ballot_sync(0xffffffffu, v2 == m2);
        int l2 = __ffs(mk2) - 1;                // lands in 0..15 (mirrored halves)
        int f = __shfl_sync(0xffffffffu, i2, l2);
        cx = sx[f * 3 + 0]; cy = sx[f * 3 + 1]; cz = sx[f * 3 + 2];
        buf ^= 1;
    }
}

// ---------------- 2) ball query ----------------
__global__ void __launch_bounds__(256) ball_kernel(const float* __restrict__ xyz,
                                                   const float* __restrict__ newxyz,
                                                   int* __restrict__ gidx) {
    const int gwarp = (blockIdx.x * blockDim.x + threadIdx.x) >> 5;
    const int lane = threadIdx.x & 31;
    if (gwarp >= NB * NPOINT) return;
    const int b = gwarp >> 10;
    const float R2 = (float)(0.2 * 0.2);

    const float cx = newxyz[gwarp * 3 + 0];
    const float cy = newxyz[gwarp * 3 + 1];
    const float cz = newxyz[gwarp * 3 + 2];
    const float* X = xyz + (size_t)b * NN * 3;
    int* out = gidx + (size_t)gwarp * NSAMPLE;

    int cnt = 0;
    int first = NN - 1;
    for (int base = 0; base < NN; base += 32) {
        int j = base + lane;
        float dx = __fsub_rn(cx, X[j * 3 + 0]);
        float dy = __fsub_rn(cy, X[j * 3 + 1]);
        float dz = __fsub_rn(cz, X[j * 3 + 2]);
        float sq = sqdist3(dx, dy, dz);
        bool in = !(sq > R2);
        unsigned mask = __ballot_sync(0xffffffffu, in);
        if (mask) {
            if (cnt == 0) first = base + __ffs(mask) - 1;
            if (in) {
                int slot = cnt + __popc(mask & ((1u << lane) - 1u));
                if (slot < NSAMPLE) out[slot] = j;
            }
            cnt += __popc(mask);
            if (cnt >= NSAMPLE) break;
        }
    }
    if (cnt < NSAMPLE && lane >= cnt) out[lane] = first;
}

// ---------------- 3) HMMA tf32 GEMM per layer (K-split, 2 stages) ----------------
// Block = 128 threads (4 warps), tile = 128 positions x 64 outputs.
// Epilogue: BN stats + (MODE3) per-query max computed from accumulator
// registers via shfl.xor trees (no serial smem scans).
// MODE 1: gather 67ch -> y1.  MODE 2: y1 -> y2.
// MODE 3: y2 -> per-query max only (no y3; BN3-affine+relu commute with max).
template <int MODE>
__global__ void __launch_bounds__(128) mma_kernel(
    const float* __restrict__ xyz, const float* __restrict__ points,
    const float* __restrict__ newxyz, const int* __restrict__ gidx,
    const float* __restrict__ yin,
    const float* __restrict__ scin, const float* __restrict__ shin,
    const float* __restrict__ W, const float* __restrict__ bias,
    float* __restrict__ yout, float* __restrict__ part) {
    constexpr int CIN = (MODE == 1) ? 67 : 64;
    constexpr int KP  = (MODE == 1) ? 72 : 64;
    constexpr int S0  = (MODE == 1) ? 40 : 32;   // stage-0 cols
    constexpr int S1  = KP - S0;                 // 32
    constexpr int STR_A = S0 + 4;                // 44 / 36
    constexpr int STR_B = KP + 4;                // 76 / 68
    constexpr int NK0 = S0 / 8, NK1 = S1 / 8;

    extern __shared__ float sm[];
    float* As = sm;                    // [128][STR_A]
    float* Bs = sm + 128 * STR_A;      // [64][STR_B]
    __shared__ float sSc[64], sSh[64], sBias[64];
    __shared__ float sNew[4][3];
    __shared__ float wS[4][64], wQ[4][64];

    const int tid = threadIdx.x;
    const int lane = tid & 31, w = tid >> 5;
    int m_tile, obase;
    if (MODE == 3) { m_tile = blockIdx.x >> 1; obase = (blockIdx.x & 1) << 6; }
    else           { m_tile = blockIdx.x;      obase = 0; }
    const int m0 = m_tile * 128;

    if (tid < 64) sBias[tid] = bias[obase + tid];
    if (MODE == 1) {
        if (tid < 12) ((float*)sNew)[tid] = newxyz[(m0 >> 5) * 3 + tid];
    } else {
        if (tid >= 64) { sSc[tid - 64] = scin[tid - 64]; sSh[tid - 64] = shin[tid - 64]; }
    }
    __syncthreads();

    // ---- B (weights, full K) ----
    for (int e = tid; e < 64 * KP; e += 128) {
        int o = e / KP, c = e - o * KP;
        Bs[o * STR_B + c] = (c < CIN) ? to_tf32(W[(obase + o) * CIN + c]) : 0.0f;
    }

    // ---- A stage 0 ----
    const int m = tid;
    float* Arow = As + m * STR_A;
    const float* Pb = nullptr;
    const float4* yrow = nullptr;
    if (MODE == 1) {
        const int bb = m0 >> 15;
        const int gi = gidx[m0 + m];
        Pb = points + ((size_t)bb * NN + gi) * 64;
        const float* Xb = xyz + ((size_t)bb * NN + gi) * 3;
        float4 t[10];
#pragma unroll
        for (int j = 0; j < 10; j++) t[j] = reinterpret_cast<const float4*>(Pb)[j];
        Arow[0] = to_tf32(__fsub_rn(Xb[0], sNew[m >> 5][0]));
        Arow[1] = to_tf32(__fsub_rn(Xb[1], sNew[m >> 5][1]));
        Arow[2] = to_tf32(__fsub_rn(Xb[2], sNew[m >> 5][2]));
#pragma unroll
        for (int c = 3; c < 40; c++) Arow[c] = to_tf32(((float*)t)[c - 3]);
    } else {
        yrow = reinterpret_cast<const float4*>(&yin[(size_t)(m0 + m) * 64]);
#pragma unroll
        for (int q = 0; q < 8; q++) {
            float4 v = yrow[q];
            int c = q * 4;
            v.x = to_tf32(fmaxf(fmaf(v.x, sSc[c + 0], sSh[c + 0]), 0.0f));
            v.y = to_tf32(fmaxf(fmaf(v.y, sSc[c + 1], sSh[c + 1]), 0.0f));
            v.z = to_tf32(fmaxf(fmaf(v.z, sSc[c + 2], sSh[c + 2]), 0.0f));
            v.w = to_tf32(fmaxf(fmaf(v.w, sSc[c + 3], sSh[c + 3]), 0.0f));
            *reinterpret_cast<float4*>(Arow + c) = v;
        }
    }
    __syncthreads();

    const int r = lane >> 2, cq = lane & 3;
    float acc[16][4];
#pragma unroll
    for (int i = 0; i < 16; i++) {
        acc[i][0] = 0.0f; acc[i][1] = 0.0f; acc[i][2] = 0.0f; acc[i][3] = 0.0f;
    }

    // ---- stage 0 MMA ----
#pragma unroll
    for (int ks = 0; ks < NK0; ks++) {
        const int kl = ks * 8;
        uint32_t a[2][4];
#pragma unroll
        for (int mt = 0; mt < 2; mt++) {
            const float* p = As + (w * 32 + mt * 16 + r) * STR_A + kl + cq;
            a[mt][0] = __float_as_uint(p[0]);
            a[mt][1] = __float_as_uint(p[8 * STR_A]);
            a[mt][2] = __float_as_uint(p[4]);
            a[mt][3] = __float_as_uint(p[8 * STR_A + 4]);
        }
#pragma unroll
        for (int nt = 0; nt < 8; nt++) {
            const float* q = Bs + (nt * 8 + r) * STR_B + kl + cq;
            uint32_t bfr[2];
            bfr[0] = __float_as_uint(q[0]);
            bfr[1] = __float_as_uint(q[4]);
            mma16n8k8(acc[nt], a[0], bfr);
            mma16n8k8(acc[8 + nt], a[1], bfr);
        }
    }
    __syncthreads();

    // ---- A stage 1 ----
    if (MODE == 1) {
        float4 t2[7];
#pragma unroll
        for (int j = 0; j < 7; j++) t2[j] = reinterpret_cast<const float4*>(Pb)[9 + j];
#pragma unroll
        for (int cc = 0; cc < 32; cc++)
            Arow[cc] = (cc < 27) ? to_tf32(((float*)t2)[cc + 1]) : 0.0f;
    } else {
#pragma unroll
        for (int q = 8; q < 16; q++) {
            float4 v = yrow[q];
            int c = q * 4;
            v.x = to_tf32(fmaxf(fmaf(v.x, sSc[c + 0], sSh[c + 0]), 0.0f));
            v.y = to_tf32(fmaxf(fmaf(v.y, sSc[c + 1], sSh[c + 1]), 0.0f));
            v.z = to_tf32(fmaxf(fmaf(v.z, sSc[c + 2], sSh[c + 2]), 0.0f));
            v.w = to_tf32(fmaxf(fmaf(v.w, sSc[c + 3], sSh[c + 3]), 0.0f));
            *reinterpret_cast<float4*>(Arow + (q - 8) * 4) = v;
        }
    }
    __syncthreads();

    // ---- stage 1 MMA ----
#pragma unroll
    for (int ks = 0; ks < NK1; ks++) {
        const int kl = ks * 8, kg = S0 + ks * 8;
        uint32_t a[2][4];
#pragma unroll
        for (int mt = 0; mt < 2; mt++) {
            const float* p = As + (w * 32 + mt * 16 + r) * STR_A + kl + cq;
            a[mt][0] = __float_as_uint(p[0]);
            a[mt][1] = __float_as_uint(p[8 * STR_A]);
            a[mt][2] = __float_as_uint(p[4]);
            a[mt][3] = __float_as_uint(p[8 * STR_A + 4]);
        }
#pragma unroll
        for (int nt = 0; nt < 8; nt++) {
            const float* q = Bs + (nt * 8 + r) * STR_B + kg + cq;
            uint32_t bfr[2];
            bfr[0] = __float_as_uint(q[0]);
            bfr[1] = __float_as_uint(q[4]);
            mma16n8k8(acc[nt], a[0], bfr);
            mma16n8k8(acc[8 + nt], a[1], bfr);
        }
    }

    // ---- register epilogue: bias + warp-level stats (and MODE3 max) ----
#pragma unroll
    for (int nt = 0; nt < 8; nt++) {
        const int col = nt * 8 + 2 * cq;
        const float b0 = sBias[col], b1 = sBias[col + 1];
        float v00 = acc[nt][0] + b0,     v01 = acc[nt][1] + b1;
        float v02 = acc[nt][2] + b0,     v03 = acc[nt][3] + b1;
        float v10 = acc[8 + nt][0] + b0, v11 = acc[8 + nt][1] + b1;
        float v12 = acc[8 + nt][2] + b0, v13 = acc[8 + nt][3] + b1;
        acc[nt][0] = v00; acc[nt][1] = v01; acc[nt][2] = v02; acc[nt][3] = v03;
        acc[8 + nt][0] = v10; acc[8 + nt][1] = v11;
        acc[8 + nt][2] = v12; acc[8 + nt][3] = v13;

        float s0 = (v00 + v02) + (v10 + v12);
        float s1 = (v01 + v03) + (v11 + v13);
        float q0 = fmaf(v00, v00, v02 * v02) + fmaf(v10, v10, v12 * v12);
        float q1 = fmaf(v01, v01, v03 * v03) + fmaf(v11, v11, v13 * v13);
        float mx0 = 0.0f, mx1 = 0.0f;
        if (MODE == 3) {
            mx0 = fmaxf(fmaxf(v00, v02), fmaxf(v10, v12));
            mx1 = fmaxf(fmaxf(v01, v03), fmaxf(v11, v13));
        }
#pragma unroll
        for (int off = 4; off <= 16; off <<= 1) {
            s0 += __shfl_xor_sync(0xffffffffu, s0, off);
            s1 += __shfl_xor_sync(0xffffffffu, s1, off);
            q0 += __shfl_xor_sync(0xffffffffu, q0, off);
            q1 += __shfl_xor_sync(0xffffffffu, q1, off);
            if (MODE == 3) {
                mx0 = fmaxf(mx0, __shfl_xor_sync(0xffffffffu, mx0, off));
                mx1 = fmaxf(mx1, __shfl_xor_sync(0xffffffffu, mx1, off));
            }
        }
        if (r == 0) {
            wS[w][col] = s0; wS[w][col + 1] = s1;
            wQ[w][col] = q0; wQ[w][col + 1] = q1;
            if (MODE == 3) {
                float* dst = yout + (size_t)((m0 >> 5) + w) * 128 + obase + col;
                dst[0] = mx0; dst[1] = mx1;
            }
        }
    }
    __syncthreads();
    if (tid < 64) {
        part[blockIdx.x * 128 + tid] =
            (wS[0][tid] + wS[1][tid]) + (wS[2][tid] + wS[3][tid]);
        part[blockIdx.x * 128 + 64 + tid] =
            (wQ[0][tid] + wQ[1][tid]) + (wQ[2][tid] + wQ[3][tid]);
    }

    if (MODE != 3) {
        float* ys = sm;
#pragma unroll
        for (int mt = 0; mt < 2; mt++) {
#pragma unroll
            for (int nt = 0; nt < 8; nt++) {
                const int row = w * 32 + mt * 16 + r;
                const int col = nt * 8 + 2 * cq;
                const float* c = acc[mt * 8 + nt];
                ys[row * 65 + col]           = c[0];
                ys[row * 65 + col + 1]       = c[1];
                ys[(row + 8) * 65 + col]     = c[2];
                ys[(row + 8) * 65 + col + 1] = c[3];
            }
        }
        __syncthreads();
        for (int e = tid; e < 8192; e += 128) {
            int mm = e >> 6, o = e & 63;
            yout[(size_t)(m0 + mm) * 64 + o] = ys[mm * 65 + o];
        }
    }
}

// ---------------- 4) BN stats reduction -> scale/shift (deterministic) ----------------
template <int NCH>
__global__ void __launch_bounds__(256) reduce_kernel(const float* __restrict__ part,
                                                     const float* __restrict__ pg,
                                                     const float* __restrict__ pbe,
                                                     float* __restrict__ scout,
                                                     float* __restrict__ shout,
                                                     int nrows) {
    const int ch = blockIdx.x;
    float s = 0.0f, ss = 0.0f;
    if (NCH == 64) {
        for (int rr = threadIdx.x; rr < nrows; rr += 256) {
            s += part[rr * 128 + ch];
            ss += part[rr * 128 + 64 + ch];
        }
    } else {
        const int p = ch >> 6, lc = ch & 63;
        const int half = nrows >> 1;
        for (int i = threadIdx.x; i < half; i += 256) {
            int rr = 2 * i + p;
            s += part[rr * 128 + lc];
            ss += part[rr * 128 + 64 + lc];
        }
    }
    __shared__ float as_[8], bs_[8];
#pragma unroll
    for (int off = 16; off; off >>= 1) {
        s += __shfl_down_sync(0xffffffffu, s, off);
        ss += __shfl_down_sync(0xffffffffu, ss, off);
    }
    const int lane = threadIdx.x & 31, wid = threadIdx.x >> 5;
    if (lane == 0) { as_[wid] = s; bs_[wid] = ss; }
    __syncthreads();
    if (threadIdx.x == 0) {
        float S = 0.0f, Q = 0.0f;
        for (int i = 0; i < 8; i++) { S += as_[i]; Q += bs_[i]; }
        float mean = S * INV_N;
        float var = Q * INV_N - mean * mean;
        float inv = rsqrtf(var + 1e-5f);
        float scv = pg[ch] * inv;
        scout[ch] = scv;
        shout[ch] = pbe[ch] - mean * scv;
    }
}

// ---------------- 5) final: BN3-affine + relu on per-query max, transpose ----------------
__global__ void __launch_bounds__(256) final_kernel(const float* __restrict__ mx,
                                                    const float* __restrict__ sc3,
                                                    const float* __restrict__ sh3,
                                                    float* __restrict__ out) {
    __shared__ float t[32][129];
    const int blk = blockIdx.x;
    const int b = blk >> 5, s0 = (blk & 31) * 32;
    const int tid = threadIdx.x;
    for (int e = tid; e < 32 * 128; e += 256) {
        int q = e >> 7, o = e & 127;
        t[q][o] = mx[(size_t)(b * 1024 + s0 + q) * 128 + o];
    }
    __syncthreads();
    for (int e = tid; e < 128 * 32; e += 256) {
        int o = e >> 5, q = e & 31;
        float v = fmaxf(fmaf(t[q][o], sc3[o], sh3[o]), 0.0f);
        out[NEWXYZ_ELEMS + (size_t)(b * 128 + o) * 1024 + s0 + q] = v;
    }
}

// ---------------- launch ----------------
extern "C" void kernel_launch(void* const* d_in, const int* in_sizes, int n_in,
                              void* d_out, int out_size) {
    const float* xyz    = (const float*)d_in[0];
    const float* points = (const float*)d_in[1];
    const float* w1 = (const float*)d_in[2];
    const float* b1 = (const float*)d_in[3];
    const float* g1 = (const float*)d_in[4];
    const float* be1 = (const float*)d_in[5];
    const float* w2 = (const float*)d_in[6];
    const float* b2 = (const float*)d_in[7];
    const float* g2 = (const float*)d_in[8];
    const float* be2 = (const float*)d_in[9];
    const float* w3 = (const float*)d_in[10];
    const float* b3 = (const float*)d_in[11];
    const float* g3 = (const float*)d_in[12];
    const float* be3 = (const float*)d_in[13];
    float* out = (float*)d_out;

    float *y1, *y2, *mx, *p1, *p2, *p3;
    float *sc1, *sh1, *sc2, *sh2, *sc3, *sh3;
    int* idx;
    cudaGetSymbolAddress((void**)&y1, g_y1);
    cudaGetSymbolAddress((void**)&y2, g_y2);
    cudaGetSymbolAddress((void**)&mx, g_mx);
    cudaGetSymbolAddress((void**)&idx, g_idx);
    cudaGetSymbolAddress((void**)&p1, g_part1);
    cudaGetSymbolAddress((void**)&p2, g_part2);
    cudaGetSymbolAddress((void**)&p3, g_part3);
    cudaGetSymbolAddress((void**)&sc1, g_sc1);
    cudaGetSymbolAddress((void**)&sh1, g_sh1);
    cudaGetSymbolAddress((void**)&sc2, g_sc2);
    cudaGetSymbolAddress((void**)&sh2, g_sh2);
    cudaGetSymbolAddress((void**)&sc3, g_sc3);
    cudaGetSymbolAddress((void**)&sh3, g_sh3);

    const int smemF = NN * 3 * 4;                      // 98304 (fps)
    const int smem1 = (128 * 44 + 64 * 76) * 4;        // 41984
    const int smem2 = (128 * 36 + 64 * 68) * 4;        // 35840
    cudaFuncSetAttribute(fps_kernel, cudaFuncAttributeMaxDynamicSharedMemorySize, smemF);
    cudaFuncSetAttribute(mma_kernel<1>, cudaFuncAttributeMaxDynamicSharedMemorySize, smem1);
    cudaFuncSetAttribute(mma_kernel<2>, cudaFuncAttributeMaxDynamicSharedMemorySize, smem2);
    cudaFuncSetAttribute(mma_kernel<3>, cudaFuncAttributeMaxDynamicSharedMemorySize, smem2);

    // 1) FPS -> new_xyz (first 49152 elems of out)
    fps_kernel<<<NB, 512, smemF>>>(xyz, out);
    // 2) ball query -> g_idx
    ball_kernel<<<(NB * NPOINT * 32) / 256, 256>>>(xyz, out, idx);
    // 3) layer1 (gather 67ch -> 64)
    mma_kernel<1><<<M_TOTAL / 128, 128, smem1>>>(
        xyz, points, out, idx, nullptr, nullptr, nullptr, w1, b1, y1, p1);
    reduce_kernel<64><<<64, 256>>>(p1, g1, be1, sc1, sh1, 4096);
    // 4) layer2 (BN1+relu fused on load)
    mma_kernel<2><<<M_TOTAL / 128, 128, smem2>>>(
        nullptr, nullptr, nullptr, nullptr, y1, sc1, sh1, w2, b2, y2, p2);
    reduce_kernel<64><<<64, 256>>>(p2, g2, be2, sc2, sh2, 4096);
    // 5) layer3 (BN2+relu fused on load); emits per-query raw max + stats
    mma_kernel<3><<<2 * (M_TOTAL / 128), 128, smem2>>>(
        nullptr, nullptr, nullptr, nullptr, y2, sc2, sh2, w3, b3, mx, p3);
    reduce_kernel<128><<<128, 256>>>(p3, g3, be3, sc3, sh3, 8192);
    // 6) BN3-affine + relu on max, transposed write
    final_kernel<<<NB * 32, 256>>>(mx, sc3, sh3, out);
}